// round 3
// baseline (speedup 1.0000x reference)
#include <cuda_runtime.h>

#define NN 10000
#define EE 320000
#define DD 256
#define NDTOT (NN*DD)

// -------- scratch (static device globals; no allocation) ----------
__device__ float g_q[NDTOT];
__device__ float g_k[NDTOT];
__device__ float g_v[NDTOT];
__device__ float g_s[NDTOT];
__device__ float g_hA[NDTOT];
__device__ float g_hB[NDTOT];
__device__ float g_mean[NDTOT];
__device__ float g_logits[EE];
__device__ int   g_rowptr[NN + 1];
__device__ int   g_srcs[EE];
__device__ int   g_cnt[NN];
__device__ int   g_fill[NN];

// =====================================================================
// Fused QKVS projection: 4 GEMMs [10000,256]x[256,256]+bias sharing A=x
// 128x128 block tile, 8x8 per thread, float4 smem loads.
// grid = (79, 8): blockIdx.y>>1 selects matrix, &1 selects N-half.
// =====================================================================
__global__ void __launch_bounds__(256, 2)
gemm_qkvs(const float* __restrict__ x,
          const float* __restrict__ Wq, const float* __restrict__ bq,
          const float* __restrict__ Wk, const float* __restrict__ bk,
          const float* __restrict__ Wv, const float* __restrict__ bv,
          const float* __restrict__ Ws, const float* __restrict__ bs)
{
    __shared__ float As[16][128];
    __shared__ float Bs[16][128];

    const int tid = threadIdx.x;
    const int tx = tid & 15, ty = tid >> 4;
    const int bm = blockIdx.x * 128;
    const int mat = blockIdx.y >> 1;
    const int bn = (blockIdx.y & 1) * 128;

    const float* B; const float* bias; float* C;
    if      (mat == 0) { B = Wq; bias = bq; C = g_q; }
    else if (mat == 1) { B = Wk; bias = bk; C = g_k; }
    else if (mat == 2) { B = Wv; bias = bv; C = g_v; }
    else               { B = Ws; bias = bs; C = g_s; }

    float acc[8][8];
#pragma unroll
    for (int i = 0; i < 8; i++)
#pragma unroll
        for (int j = 0; j < 8; j++) acc[i][j] = 0.f;

    const int arow = tid & 127;
    const int ak0  = (tid >> 7) * 8;
    const int brow = tid >> 4;
    const int bcol = (tid & 15) * 8;
    const bool avalid = (bm + arow) < NN;
    const float* aptr = x + (size_t)(bm + arow) * DD + ak0;
    const float* bptr = B + (size_t)brow * DD + bn + bcol;

    for (int kt = 0; kt < 256; kt += 16) {
        float4 a0 = make_float4(0.f,0.f,0.f,0.f), a1 = a0;
        if (avalid) {
            a0 = *reinterpret_cast<const float4*>(aptr + kt);
            a1 = *reinterpret_cast<const float4*>(aptr + kt + 4);
        }
        As[ak0+0][arow]=a0.x; As[ak0+1][arow]=a0.y; As[ak0+2][arow]=a0.z; As[ak0+3][arow]=a0.w;
        As[ak0+4][arow]=a1.x; As[ak0+5][arow]=a1.y; As[ak0+6][arow]=a1.z; As[ak0+7][arow]=a1.w;
        float4 b0 = *reinterpret_cast<const float4*>(bptr + (size_t)kt * DD);
        float4 b1 = *reinterpret_cast<const float4*>(bptr + (size_t)kt * DD + 4);
        *reinterpret_cast<float4*>(&Bs[brow][bcol])     = b0;
        *reinterpret_cast<float4*>(&Bs[brow][bcol + 4]) = b1;
        __syncthreads();
#pragma unroll
        for (int kk = 0; kk < 16; kk++) {
            float4 av0 = *reinterpret_cast<const float4*>(&As[kk][ty*8]);
            float4 av1 = *reinterpret_cast<const float4*>(&As[kk][ty*8+4]);
            float4 bv0 = *reinterpret_cast<const float4*>(&Bs[kk][tx*8]);
            float4 bv1 = *reinterpret_cast<const float4*>(&Bs[kk][tx*8+4]);
            float a[8] = {av0.x,av0.y,av0.z,av0.w,av1.x,av1.y,av1.z,av1.w};
            float b[8] = {bv0.x,bv0.y,bv0.z,bv0.w,bv1.x,bv1.y,bv1.z,bv1.w};
#pragma unroll
            for (int i = 0; i < 8; i++)
#pragma unroll
                for (int j = 0; j < 8; j++)
                    acc[i][j] = fmaf(a[i], b[j], acc[i][j]);
        }
        __syncthreads();
    }

    float4 bi0 = *reinterpret_cast<const float4*>(&bias[bn + tx*8]);
    float4 bi1 = *reinterpret_cast<const float4*>(&bias[bn + tx*8 + 4]);
    float bb[8] = {bi0.x,bi0.y,bi0.z,bi0.w,bi1.x,bi1.y,bi1.z,bi1.w};
#pragma unroll
    for (int i = 0; i < 8; i++) {
        int row = bm + ty*8 + i;
        if (row < NN) {
            float4 o0, o1;
            o0.x=acc[i][0]+bb[0]; o0.y=acc[i][1]+bb[1]; o0.z=acc[i][2]+bb[2]; o0.w=acc[i][3]+bb[3];
            o1.x=acc[i][4]+bb[4]; o1.y=acc[i][5]+bb[5]; o1.z=acc[i][6]+bb[6]; o1.w=acc[i][7]+bb[7];
            *reinterpret_cast<float4*>(&C[(size_t)row*DD + bn + tx*8])     = o0;
            *reinterpret_cast<float4*>(&C[(size_t)row*DD + bn + tx*8 + 4]) = o1;
        }
    }
}

// =====================================================================
// Fused SAGE layer: z = mean@Wl + bl + hin@Wr (K=512 virtual concat),
// epilogue: z*BNS*gamma+beta, gated residual with hin, relu -> hout.
// =====================================================================
__global__ void __launch_bounds__(256, 2)
gemm_sage(const float* __restrict__ Wl, const float* __restrict__ bl,
          const float* __restrict__ Wr,
          const float* __restrict__ gamma, const float* __restrict__ beta,
          const float* __restrict__ alpha,
          const float* __restrict__ hin, float* __restrict__ hout)
{
    __shared__ float As[16][128];
    __shared__ float Bs[16][128];

    const int tid = threadIdx.x;
    const int tx = tid & 15, ty = tid >> 4;
    const int bm = blockIdx.x * 128;
    const int bn = blockIdx.y * 128;

    float acc[8][8];
#pragma unroll
    for (int i = 0; i < 8; i++)
#pragma unroll
        for (int j = 0; j < 8; j++) acc[i][j] = 0.f;

    const int arow = tid & 127;
    const int ak0  = (tid >> 7) * 8;
    const int brow = tid >> 4;
    const int bcol = (tid & 15) * 8;
    const bool avalid = (bm + arow) < NN;

    for (int kt = 0; kt < 512; kt += 16) {
        const float* Asrc = (kt < 256) ? g_mean : hin;
        const float* Bsrc = (kt < 256) ? Wl : Wr;
        const int kc = kt & 255;
        float4 a0 = make_float4(0.f,0.f,0.f,0.f), a1 = a0;
        if (avalid) {
            const float* ap = Asrc + (size_t)(bm + arow) * DD + kc + ak0;
            a0 = *reinterpret_cast<const float4*>(ap);
            a1 = *reinterpret_cast<const float4*>(ap + 4);
        }
        As[ak0+0][arow]=a0.x; As[ak0+1][arow]=a0.y; As[ak0+2][arow]=a0.z; As[ak0+3][arow]=a0.w;
        As[ak0+4][arow]=a1.x; As[ak0+5][arow]=a1.y; As[ak0+6][arow]=a1.z; As[ak0+7][arow]=a1.w;
        const float* bp = Bsrc + (size_t)(kc + brow) * DD + bn + bcol;
        float4 b0 = *reinterpret_cast<const float4*>(bp);
        float4 b1 = *reinterpret_cast<const float4*>(bp + 4);
        *reinterpret_cast<float4*>(&Bs[brow][bcol])     = b0;
        *reinterpret_cast<float4*>(&Bs[brow][bcol + 4]) = b1;
        __syncthreads();
#pragma unroll
        for (int kk = 0; kk < 16; kk++) {
            float4 av0 = *reinterpret_cast<const float4*>(&As[kk][ty*8]);
            float4 av1 = *reinterpret_cast<const float4*>(&As[kk][ty*8+4]);
            float4 bv0 = *reinterpret_cast<const float4*>(&Bs[kk][tx*8]);
            float4 bv1 = *reinterpret_cast<const float4*>(&Bs[kk][tx*8+4]);
            float a[8] = {av0.x,av0.y,av0.z,av0.w,av1.x,av1.y,av1.z,av1.w};
            float b[8] = {bv0.x,bv0.y,bv0.z,bv0.w,bv1.x,bv1.y,bv1.z,bv1.w};
#pragma unroll
            for (int i = 0; i < 8; i++)
#pragma unroll
                for (int j = 0; j < 8; j++)
                    acc[i][j] = fmaf(a[i], b[j], acc[i][j]);
        }
        __syncthreads();
    }

    // epilogue: bias + BN(eval) + gated residual + relu
    const float al  = 1.f / (1.f + __expf(-alpha[0]));
    const float oma = 1.f - al;
    const float BNS = 0.9999950000374994f;   // 1/sqrt(1+1e-5)
    const int col0 = bn + tx*8;
    float4 bl0 = *reinterpret_cast<const float4*>(&bl[col0]);
    float4 bl1 = *reinterpret_cast<const float4*>(&bl[col0 + 4]);
    float4 g0  = *reinterpret_cast<const float4*>(&gamma[col0]);
    float4 g1  = *reinterpret_cast<const float4*>(&gamma[col0 + 4]);
    float4 be0 = *reinterpret_cast<const float4*>(&beta[col0]);
    float4 be1 = *reinterpret_cast<const float4*>(&beta[col0 + 4]);
    float blv[8] = {bl0.x,bl0.y,bl0.z,bl0.w,bl1.x,bl1.y,bl1.z,bl1.w};
    float gv[8]  = {g0.x,g0.y,g0.z,g0.w,g1.x,g1.y,g1.z,g1.w};
    float bev[8] = {be0.x,be0.y,be0.z,be0.w,be1.x,be1.y,be1.z,be1.w};

#pragma unroll
    for (int i = 0; i < 8; i++) {
        int row = bm + ty*8 + i;
        if (row < NN) {
            float4 r0 = *reinterpret_cast<const float4*>(&hin[(size_t)row*DD + col0]);
            float4 r1 = *reinterpret_cast<const float4*>(&hin[(size_t)row*DD + col0 + 4]);
            float rv[8] = {r0.x,r0.y,r0.z,r0.w,r1.x,r1.y,r1.z,r1.w};
            float o[8];
#pragma unroll
            for (int j = 0; j < 8; j++) {
                float zz = fmaf((acc[i][j] + blv[j]) * BNS, gv[j], bev[j]);
                o[j] = fmaxf(fmaf(al, zz, oma * rv[j]), 0.f);
            }
            float4 o0 = make_float4(o[0],o[1],o[2],o[3]);
            float4 o1 = make_float4(o[4],o[5],o[6],o[7]);
            *reinterpret_cast<float4*>(&hout[(size_t)row*DD + col0])     = o0;
            *reinterpret_cast<float4*>(&hout[(size_t)row*DD + col0 + 4]) = o1;
        }
    }
}

// -------- CSR build ----------
__global__ void zero_cnt_kernel()
{
    int i = blockIdx.x * blockDim.x + threadIdx.x;
    if (i < NN) g_cnt[i] = 0;
}

__global__ void hist_kernel(const int* __restrict__ ei)
{
    int e = blockIdx.x * blockDim.x + threadIdx.x;
    if (e >= EE) return;
    atomicAdd(&g_cnt[ei[EE + e]], 1);
}

__global__ void scan_kernel()
{
    __shared__ int sh[1024];
    __shared__ int carry;
    int tid = threadIdx.x;
    if (tid == 0) { carry = 0; g_rowptr[0] = 0; }
    __syncthreads();
    for (int base = 0; base < NN; base += 1024) {
        int i = base + tid;
        int v = (i < NN) ? g_cnt[i] : 0;
        sh[tid] = v;
        __syncthreads();
        for (int off = 1; off < 1024; off <<= 1) {
            int t = (tid >= off) ? sh[tid - off] : 0;
            __syncthreads();
            sh[tid] += t;
            __syncthreads();
        }
        int incl = sh[tid] + carry;
        if (i < NN) {
            g_rowptr[i + 1] = incl;
            g_fill[i] = incl - v;   // exclusive
        }
        __syncthreads();
        if (tid == 1023) carry = incl;
        __syncthreads();
    }
}

__global__ void scatter_kernel(const int* __restrict__ ei)
{
    int e = blockIdx.x * blockDim.x + threadIdx.x;
    if (e >= EE) return;
    int src = ei[e];
    int dst = ei[EE + e];
    int pos = atomicAdd(&g_fill[dst], 1);
    g_srcs[pos] = src;
}

// -------- TransformerConv: warp per node, 2-pass softmax aggregation ----------
__global__ void attn_kernel()
{
    int gw = (blockIdx.x * blockDim.x + threadIdx.x) >> 5;
    int lane = threadIdx.x & 31;
    if (gw >= NN) return;
    int beg = g_rowptr[gw], end = g_rowptr[gw + 1];

    float qr[8];
#pragma unroll
    for (int r = 0; r < 8; r++) qr[r] = g_q[(size_t)gw * DD + r * 32 + lane];

    float m = -1e30f;
    for (int e = beg; e < end; e++) {
        int src = g_srcs[e];
        const float* kp = &g_k[(size_t)src * DD];
        float p = 0.f;
#pragma unroll
        for (int r = 0; r < 8; r++) p = fmaf(qr[r], kp[r * 32 + lane], p);
#pragma unroll
        for (int off = 16; off; off >>= 1) p += __shfl_xor_sync(0xffffffffu, p, off);
        p *= 0.0625f;                 // / sqrt(256)
        if (lane == 0) g_logits[e] = p;
        m = fmaxf(m, p);
    }

    float acc[8];
#pragma unroll
    for (int r = 0; r < 8; r++) acc[r] = 0.f;
    float ssum = 0.f;
    for (int e = beg; e < end; e++) {
        int src = g_srcs[e];
        float w = __expf(g_logits[e] - m);
        ssum += w;
        const float* vp = &g_v[(size_t)src * DD];
#pragma unroll
        for (int r = 0; r < 8; r++) acc[r] = fmaf(w, vp[r * 32 + lane], acc[r]);
    }

    float inv = (end > beg) ? (1.f / ssum) : 0.f;
#pragma unroll
    for (int r = 0; r < 8; r++) {
        float val = acc[r] * inv + g_s[(size_t)gw * DD + r * 32 + lane];
        g_hA[(size_t)gw * DD + r * 32 + lane] = fmaxf(val, 0.f);
    }
}

// -------- SAGE mean aggregation: warp per node ----------
__global__ void mean_kernel(const float* __restrict__ h)
{
    int gw = (blockIdx.x * blockDim.x + threadIdx.x) >> 5;
    int lane = threadIdx.x & 31;
    if (gw >= NN) return;
    int beg = g_rowptr[gw], end = g_rowptr[gw + 1];

    float acc[8];
#pragma unroll
    for (int r = 0; r < 8; r++) acc[r] = 0.f;
    for (int e = beg; e < end; e++) {
        int src = g_srcs[e];
        const float* hp = &h[(size_t)src * DD];
#pragma unroll
        for (int r = 0; r < 8; r++) acc[r] += hp[r * 32 + lane];
    }
    int deg = end - beg;
    float inv = 1.f / (float)(deg > 0 ? deg : 1);
#pragma unroll
    for (int r = 0; r < 8; r++)
        g_mean[(size_t)gw * DD + r * 32 + lane] = acc[r] * inv;
}

// -------- launch ----------
extern "C" void kernel_launch(void* const* d_in, const int* in_sizes, int n_in,
                              void* d_out, int out_size)
{
    const float* x     = (const float*)d_in[0];
    const int*   ei    = (const int*)d_in[1];       // int32 (jax x64 disabled)
    const float* Wq    = (const float*)d_in[2];
    const float* bq    = (const float*)d_in[3];
    const float* Wk    = (const float*)d_in[4];
    const float* bk    = (const float*)d_in[5];
    const float* Wv    = (const float*)d_in[6];
    const float* bv    = (const float*)d_in[7];
    const float* Ws    = (const float*)d_in[8];
    const float* bs    = (const float*)d_in[9];
    const float* Wl    = (const float*)d_in[10];
    const float* bl    = (const float*)d_in[11];
    const float* Wr    = (const float*)d_in[12];
    const float* gamma = (const float*)d_in[13];
    const float* beta  = (const float*)d_in[14];
    const float* alpha = (const float*)d_in[15];
    float*       out   = (float*)d_out;

    float *hA, *hB;
    cudaGetSymbolAddress((void**)&hA, g_hA);
    cudaGetSymbolAddress((void**)&hB, g_hB);

    const int MT = (NN + 127) / 128;   // 79

    // CSR build (independent of projections; launch first for overlap-free order)
    zero_cnt_kernel<<<(NN + 255) / 256, 256>>>();
    hist_kernel<<<(EE + 255) / 256, 256>>>(ei);
    scan_kernel<<<1, 1024>>>();
    scatter_kernel<<<(EE + 255) / 256, 256>>>(ei);

    // fused projections
    gemm_qkvs<<<dim3(MT, 8), 256>>>(x, Wq, bq, Wk, bk, Wv, bv, Ws, bs);

    // TransformerConv
    attn_kernel<<<(NN * 32 + 255) / 256, 256>>>();

    // 3 fused SAGE layers
    float* hin = hA;
    for (int l = 0; l < 3; l++) {
        mean_kernel<<<(NN * 32 + 255) / 256, 256>>>(hin);
        float* hout = (l == 2) ? out : ((l == 0) ? hB : hA);
        gemm_sage<<<dim3(MT, 2), 256>>>(Wl + (size_t)l * 65536, bl + (size_t)l * 256,
                                        Wr + (size_t)l * 65536,
                                        gamma + (size_t)l * 256, beta + (size_t)l * 256,
                                        alpha, hin, hout);
        hin = hout;
    }
}